// round 13
// baseline (speedup 1.0000x reference)
#include <cuda_runtime.h>
#include <cuda_fp16.h>
#include <cstdint>
#include <cstddef>

#define TSTEPS 512
#define NB     128
#define DIN    1024
#define DH     1024
#define NR     256
#define N4     4096
#define NSPAR  768
#define RCTAS  128        // 2 batch-halves x 64 N-tiles
#define KCH    128
#define NCH    8          // DH/KCH
#define HSTRB  272        // h row stride bytes (256 data + 16 pad)
#define WSTRB  288        // W k-pair row stride bytes (256 data + 32 pad)
#define HCHUNK (64 * HSTRB)          // 17408 per h stage
#define NSTG   4
#define WOFF   (NSTG * HCHUNK)       // 69632
#define WFULL  (512 * WSTRB)         // 147456
#define RNN_SMEM (WOFF + WFULL)      // 217088
// xgemm fp16 staging
#define XASTR  144
#define XBSTR  544
#define XSTG_BYTES (128 * XASTR + 32 * XBSTR)  // 35840
#define XG_SMEM (4 * XSTG_BYTES)               // 143360

// ---- static device scratch ----
__device__ float g_Wx[(size_t)N4 * DIN];
__device__ float g_Wh[(size_t)N4 * DH];
__device__ float g_bias[N4];
__device__ float g_preX[(size_t)TSTEPS * NB * N4];          // 1 GiB
__device__ __half g_xh[(size_t)TSTEPS * NB * DIN];          // x in fp16
__device__ __half g_Wxh[(size_t)32 * 512 * 256];            // [nblk][kpair][n*2+par]
__device__ __half g_Whs[(size_t)64 * 512 * 128];            // [ntile][kpair][n*2+par]
__device__ __half g_h[2][NB * DH];                          // h ping-pong (fp16)
__device__ unsigned g_barg[8];
__device__ unsigned g_root2[64];                            // per-bhalf root (stride 32)

// ================= helpers =================
__device__ __forceinline__ void mma_f16(float* c, const uint32_t* a, const uint32_t* b) {
    asm volatile("mma.sync.aligned.m16n8k16.row.col.f32.f16.f16.f32 "
                 "{%0,%1,%2,%3}, {%4,%5,%6,%7}, {%8,%9}, {%0,%1,%2,%3};"
                 : "+f"(c[0]), "+f"(c[1]), "+f"(c[2]), "+f"(c[3])
                 : "r"(a[0]), "r"(a[1]), "r"(a[2]), "r"(a[3]), "r"(b[0]), "r"(b[1]));
}
__device__ __forceinline__ void ldsm4(uint32_t* r, uint32_t addr) {
    asm volatile("ldmatrix.sync.aligned.m8n8.x4.shared.b16 {%0,%1,%2,%3}, [%4];"
                 : "=r"(r[0]), "=r"(r[1]), "=r"(r[2]), "=r"(r[3]) : "r"(addr));
}
__device__ __forceinline__ float fsigmoid(float x) { return 1.0f / (1.0f + __expf(-x)); }

__device__ __forceinline__ uint32_t smem_u32(const void* p) {
    uint32_t a;
    asm("{ .reg .u64 t; cvta.to.shared.u64 t, %1; cvt.u32.u64 %0, t; }" : "=r"(a) : "l"(p));
    return a;
}
__device__ __forceinline__ void cp16(uint32_t dst, const void* src) {
    asm volatile("cp.async.cg.shared.global [%0], [%1], 16;" :: "r"(dst), "l"(src));
}
__device__ __forceinline__ unsigned ld_acq(const unsigned* p) {
    unsigned v;
    asm volatile("ld.acquire.gpu.global.u32 %0, [%1];" : "=r"(v) : "l"(p) : "memory");
    return v;
}
#define CP_COMMIT() asm volatile("cp.async.commit_group;" ::: "memory")
#define CP_WAIT(n)  asm volatile("cp.async.wait_group %0;" :: "n"(n) : "memory")

// ================= prep kernels (fused) =================
__global__ void k_prep0(const float* __restrict__ h0,
                        const float* __restrict__ Ax, const float* __restrict__ Ah,
                        const float* __restrict__ bx, const float* __restrict__ bh) {
    int i = blockIdx.x * blockDim.x + threadIdx.x;
    if (i < 4 * NR * DIN) {
        int k = i % DIN, row = i / DIN;
        int g = row / NR, j = row % NR;
        size_t w = ((size_t)(g * DH + j)) * DIN + k;
        g_Wx[w] = Ax[i];
        g_Wh[w] = Ah[i];
    }
    if (i < N4) g_bias[i] = bx[i] + bh[i];
    if (i < NB * DH) g_h[0][i] = __float2half_rn(h0[i]);
    if (i < 8) g_barg[i] = 0;
    if (i < 64) g_root2[i] = 0;
}

__global__ void k_spar(const float* __restrict__ Bx, const float* __restrict__ Cx,
                       const float* __restrict__ Bh, const float* __restrict__ Ch) {
    int z = blockIdx.z;
    int g = z & 3;
    const float* Bp = (z < 4) ? Bx : Bh;
    const float* Cp = (z < 4) ? Cx : Ch;
    float*       Wp = (z < 4) ? g_Wx : g_Wh;
    int m0  = blockIdx.y * 8;
    int col = blockIdx.x * 128 + threadIdx.x;

    __shared__ float Bs[8][NR];
    for (int i = threadIdx.x; i < 8 * NR; i += 128) {
        int mm = i / NR, rr = i % NR;
        Bs[mm][rr] = Bp[(size_t)(g * NSPAR + m0 + mm) * NR + rr];
    }
    __syncthreads();
    float acc[8];
#pragma unroll
    for (int mm = 0; mm < 8; mm++) acc[mm] = 0.0f;
    for (int r = 0; r < NR; ++r) {
        float cv = Cp[(size_t)(g * NR + r) * DIN + col];
#pragma unroll
        for (int mm = 0; mm < 8; mm++) acc[mm] += Bs[mm][r] * cv;
    }
#pragma unroll
    for (int mm = 0; mm < 8; mm++)
        Wp[(size_t)(g * DH + NR + m0 + mm) * DIN + col] = acc[mm];
}

// fused: pack Wh, pack Wx, convert x (16 x-elems per thread). 4,194,304 threads.
__global__ void k_prep1(const float* __restrict__ x) {
    int i = blockIdx.x * blockDim.x + threadIdx.x;
    if (i >= 64 * DH * 64) return;
    {   // Wh pack
        int n = i & 63, k = (i >> 6) & (DH - 1), ntile = i >> 16;
        int ng = (n >> 4) * DH + ntile * 16 + (n & 15);
        size_t dst = ((size_t)ntile * 512 + (k >> 1)) * 128 + n * 2 + (k & 1);
        g_Whs[dst] = __float2half_rn(g_Wh[(size_t)ng * DH + k]);
    }
    {   // Wx pack
        int k = i & (DIN - 1), n = i >> 10;
        int nb = n >> 7, nl = n & 127;
        size_t dst = ((size_t)nb * 512 + (k >> 1)) * 256 + nl * 2 + (k & 1);
        g_Wxh[dst] = __float2half_rn(g_Wx[(size_t)n * DIN + k]);
    }
    {   // x convert: 16 elems
        size_t base = (size_t)i * 16;
#pragma unroll
        for (int p = 0; p < 4; p++) {
            float4 v = *(const float4*)&x[base + p * 4];
            *(__half2*)&g_xh[base + p * 4]     = __floats2half2_rn(v.x, v.y);
            *(__half2*)&g_xh[base + p * 4 + 2] = __floats2half2_rn(v.z, v.w);
        }
    }
}

// ---------------- X GEMM fp16: preX = x @ Wx^T + bias ----------------
// 4-stage ring, 1 sync/chunk, ldmatrix A.
__global__ __launch_bounds__(256) void k_xgemm16() {
    extern __shared__ char xsm[];
    const int tid  = threadIdx.x;
    const int lane = tid & 31;
    const int warp = tid >> 5;
    const int wm   = warp & 1;
    const int wn   = warp >> 1;
    const int q    = lane & 3;
    const size_t mBase = (size_t)blockIdx.y * 128;
    const int    nb    = blockIdx.x;
    const uint32_t xb  = smem_u32(xsm);

    auto issue = [&](int cc) {
        uint32_t sb = xb + (cc & 3) * XSTG_BYTES;
#pragma unroll
        for (int i = 0; i < 8; i++) {
            int s = tid + i * 256;
            if (s < 1024) {
                int r = s >> 3, seg = s & 7;
                cp16(sb + (uint32_t)(r * XASTR + seg * 16),
                     &g_xh[(mBase + r) * DIN + cc * 64 + seg * 8]);
            } else {
                int v = s - 1024;
                int kl = v >> 5, seg = v & 31;
                cp16(sb + (uint32_t)(128 * XASTR + kl * XBSTR + seg * 16),
                     &g_Wxh[((size_t)nb * 512 + cc * 32 + kl) * 256 + seg * 8]);
            }
        }
        CP_COMMIT();
    };

    issue(0); issue(1); issue(2);

    float acc[4][4][4];
#pragma unroll
    for (int a = 0; a < 4; a++)
#pragma unroll
        for (int b = 0; b < 4; b++)
#pragma unroll
            for (int d = 0; d < 4; d++) acc[a][b][d] = 0.0f;

    const int lrow = (lane & 7) + ((lane >> 3) & 1) * 8;
    const int lcol = (lane >> 4) * 8;

    for (int ch = 0; ch < 16; ++ch) {
        if (ch <= 13)      CP_WAIT(2);
        else if (ch == 14) CP_WAIT(1);
        else               CP_WAIT(0);
        __syncthreads();
        if (ch + 3 < 16) issue(ch + 3);

        const uint32_t hsb = xb + (ch & 3) * XSTG_BYTES;
        const char* WsB = xsm + (ch & 3) * XSTG_BYTES + 128 * XASTR;
#pragma unroll
        for (int k16 = 0; k16 < 4; k16++) {
            const int kb = k16 * 16;
            uint32_t af[4][4];
#pragma unroll
            for (int mf = 0; mf < 4; mf++) {
                uint32_t ad = hsb + (uint32_t)((wm * 64 + mf * 16 + lrow) * XASTR + (kb + lcol) * 2);
                ldsm4(af[mf], ad);
            }
#pragma unroll
            for (int nf = 0; nf < 4; nf++) {
                uint32_t bf[2];
                int n0 = wn * 32 + nf * 8 + (lane >> 2);
                bf[0] = *(const uint32_t*)(WsB + (kb / 2 + q) * XBSTR + n0 * 4);
                bf[1] = *(const uint32_t*)(WsB + (kb / 2 + 4 + q) * XBSTR + n0 * 4);
#pragma unroll
                for (int mf = 0; mf < 4; mf++)
                    mma_f16(acc[mf][nf], af[mf], bf);
            }
        }
    }

    const int nBase = nb * 128;
#pragma unroll
    for (int mf = 0; mf < 4; mf++) {
#pragma unroll
        for (int nf = 0; nf < 4; nf++) {
            int r0 = wm * 64 + mf * 16 + (lane >> 2);
            int c0 = wn * 32 + nf * 8 + (lane & 3) * 2;
            int n  = nBase + c0;
            size_t base = (mBase + r0) * (size_t)N4 + n;
            g_preX[base]                      = acc[mf][nf][0] + g_bias[n];
            g_preX[base + 1]                  = acc[mf][nf][1] + g_bias[n + 1];
            g_preX[base + 8 * (size_t)N4]     = acc[mf][nf][2] + g_bias[n];
            g_preX[base + 8 * (size_t)N4 + 1] = acc[mf][nf][3] + g_bias[n + 1];
        }
    }
}

// ---------------- persistent M-split fp16 recurrence, W resident, 4-stage ring ----------------
__global__ __launch_bounds__(256) void k_rnn(const float* __restrict__ c0,
                                             float* __restrict__ out) {
    extern __shared__ char dsm[];
    const int tid   = threadIdx.x;
    const int lane  = tid & 31;
    const int warp  = tid >> 5;
    const int cta   = blockIdx.x;
    const int ntile = cta & 63;
    const int bhalf = cta >> 6;
    const int bh64  = bhalf * 64;
    const int wq    = warp & 3;
    const int kpar  = warp >> 2;
    const int wm    = wq & 1;
    const int wn    = wq >> 1;
    const int q     = lane & 3;
    float* Psa = (float*)dsm;                    // overlay on h stage 0
    float* Psb = (float*)(dsm + HCHUNK);         // overlay on h stage 1

    const uint32_t dynb = smem_u32(dsm);

    const int er = tid & 63;
    const int ug = tid >> 6;
    const int eb = bh64 + er;
    const int lrow = (lane & 7) + ((lane >> 3) & 1) * 8;
    const int lcol = (lane >> 4) * 8;

    // load resident W
    for (int i = tid; i < 8192; i += 256) {
        int row = i >> 4, seg = i & 15;
        cp16(dynb + (uint32_t)(WOFF + row * WSTRB + seg * 16),
             &g_Whs[((size_t)ntile * 512 + row) * 128 + seg * 8]);
    }
    CP_COMMIT();

    float cst[4];
    {
        float4 cv = *(const float4*)&c0[(size_t)eb * DH + ntile * 16 + ug * 4];
        cst[0] = cv.x; cst[1] = cv.y; cst[2] = cv.z; cst[3] = cv.w;
    }
    CP_WAIT(0);
    __syncthreads();

    for (int t = 0; t < TSTEPS; ++t) {
        const int src = t & 1;
        const __half* __restrict__ hsrc = g_h[src];

        auto issue = [&](int cc) {
            uint32_t sb = dynb + (cc & 3) * HCHUNK;
#pragma unroll
            for (int i = 0; i < 4; i++) {
                int s = tid + i * 256;
                int r = s >> 4, seg = s & 15;
                cp16(sb + (uint32_t)(r * HSTRB + seg * 16),
                     &hsrc[(size_t)(bh64 + r) * DH + cc * KCH + seg * 8]);
            }
            CP_COMMIT();
        };

        issue(0); issue(1); issue(2);

        float4 px[4];
        {
            size_t pxb = ((size_t)t * NB + eb) * N4 + ntile * 16 + ug * 4;
#pragma unroll
            for (int g = 0; g < 4; g++)
                px[g] = *(const float4*)&g_preX[pxb + (size_t)g * DH];
        }

        float acc[2][4][4];
#pragma unroll
        for (int a = 0; a < 2; a++)
#pragma unroll
            for (int c = 0; c < 4; c++)
#pragma unroll
                for (int d = 0; d < 4; d++) acc[a][c][d] = 0.0f;

        for (int ch = 0; ch < NCH; ++ch) {
            if (ch <= NCH - 3)      CP_WAIT(2);
            else if (ch == NCH - 2) CP_WAIT(1);
            else                    CP_WAIT(0);
            __syncthreads();
            if (ch + 3 < NCH) issue(ch + 3);

            const uint32_t hsb = dynb + (ch & 3) * HCHUNK;
            const char* WsB = dsm + WOFF + ch * 64 * WSTRB;
#pragma unroll
            for (int k16 = 0; k16 < 8; k16 += 2) {
                const int kb = (k16 + kpar) * 16;
                uint32_t af[2][4];
#pragma unroll
                for (int mf = 0; mf < 2; mf++) {
                    uint32_t ad = hsb + (uint32_t)((wm * 32 + mf * 16 + lrow) * HSTRB + (kb + lcol) * 2);
                    ldsm4(af[mf], ad);
                }
#pragma unroll
                for (int nf = 0; nf < 4; nf++) {
                    uint32_t bf[2];
                    int n0 = wn * 32 + nf * 8 + (lane >> 2);
                    bf[0] = *(const uint32_t*)(WsB + (kb / 2 + q) * WSTRB + n0 * 4);
                    bf[1] = *(const uint32_t*)(WsB + (kb / 2 + 4 + q) * WSTRB + n0 * 4);
#pragma unroll
                    for (int mf = 0; mf < 2; mf++)
                        mma_f16(acc[mf][nf], af[mf], bf);
                }
            }
        }
        __syncthreads();   // all warps done reading stages before Ps overlay

        // single-sync merge: kpar groups store to disjoint Ps arrays
        {
            float* Pd = (kpar == 0) ? Psa : Psb;
#pragma unroll
            for (int mf = 0; mf < 2; mf++) {
#pragma unroll
                for (int nf = 0; nf < 4; nf++) {
                    int r0 = wm * 32 + mf * 16 + (lane >> 2);
                    int c0i = wn * 32 + nf * 8 + q * 2;
                    Pd[r0 * 68 + c0i]           = acc[mf][nf][0];
                    Pd[r0 * 68 + c0i + 1]       = acc[mf][nf][1];
                    Pd[(r0 + 8) * 68 + c0i]     = acc[mf][nf][2];
                    Pd[(r0 + 8) * 68 + c0i + 1] = acc[mf][nf][3];
                }
            }
        }
        __syncthreads();

        // pointwise LSTM
        float hv[4];
        {
            float4 pa0 = *(const float4*)&Psa[er * 68 + ug * 4];
            float4 pa1 = *(const float4*)&Psa[er * 68 + 16 + ug * 4];
            float4 pa2 = *(const float4*)&Psa[er * 68 + 32 + ug * 4];
            float4 pa3 = *(const float4*)&Psa[er * 68 + 48 + ug * 4];
            float4 pb0 = *(const float4*)&Psb[er * 68 + ug * 4];
            float4 pb1 = *(const float4*)&Psb[er * 68 + 16 + ug * 4];
            float4 pb2 = *(const float4*)&Psb[er * 68 + 32 + ug * 4];
            float4 pb3 = *(const float4*)&Psb[er * 68 + 48 + ug * 4];
#pragma unroll
            for (int i = 0; i < 4; i++) {
                float f  = fsigmoid(((const float*)&pa0)[i] + ((const float*)&pb0)[i] + ((const float*)&px[0])[i]);
                float ii = fsigmoid(((const float*)&pa1)[i] + ((const float*)&pb1)[i] + ((const float*)&px[1])[i]);
                float gg = tanhf(((const float*)&pa2)[i] + ((const float*)&pb2)[i] + ((const float*)&px[2])[i]);
                float oo = fsigmoid(((const float*)&pa3)[i] + ((const float*)&pb3)[i] + ((const float*)&px[3])[i]);
                float nc = f * cst[i] + ii * gg;
                cst[i] = nc;
                hv[i] = oo * tanhf(nc);
            }
            // h ping-pong store FIRST (covered by fence)
            __half* __restrict__ hdst = g_h[src ^ 1];
            size_t hb = (size_t)eb * DH + ntile * 16 + ug * 4;
            *(__half2*)&hdst[hb]     = __floats2half2_rn(hv[0], hv[1]);
            *(__half2*)&hdst[hb + 2] = __floats2half2_rn(hv[2], hv[3]);
        }

        __threadfence();
        __syncthreads();
        if (tid == 0) {
            unsigned r = atomicAdd(&g_barg[cta >> 4], 1u);
            if (r == 16u * (unsigned)(t + 1) - 1u) {
                __threadfence();
                atomicAdd(&g_root2[bhalf * 32], 1u);
            }
        }
        // out stores overlap the barrier spin
        {
            size_t oo = ((size_t)t * NB + eb) * DH + ntile * 16 + ug * 4;
            *(float4*)&out[oo] = make_float4(hv[0], hv[1], hv[2], hv[3]);
            if (t == TSTEPS - 1) {
                size_t fb = (size_t)TSTEPS * NB * DH + (size_t)eb * DH + ntile * 16 + ug * 4;
                *(float4*)&out[fb] = make_float4(hv[0], hv[1], hv[2], hv[3]);
                *(float4*)&out[fb + (size_t)NB * DH] = make_float4(cst[0], cst[1], cst[2], cst[3]);
            }
        }
        if (tid == 0) {
            while (ld_acq(&g_root2[bhalf * 32]) < 4u * (unsigned)(t + 1)) { }
        }
        __syncthreads();
    }
}

// ---------------- launch ----------------
extern "C" void kernel_launch(void* const* d_in, const int* in_sizes, int n_in,
                              void* d_out, int out_size) {
    const float* x  = (const float*)d_in[0];
    const float* h0 = (const float*)d_in[1];
    const float* c0 = (const float*)d_in[2];
    const float* Ax = (const float*)d_in[3];
    const float* Bx = (const float*)d_in[4];
    const float* Cx = (const float*)d_in[5];
    const float* Ah = (const float*)d_in[6];
    const float* Bh = (const float*)d_in[7];
    const float* Ch = (const float*)d_in[8];
    const float* bx = (const float*)d_in[9];
    const float* bh = (const float*)d_in[10];
    float* out = (float*)d_out;

    cudaFuncSetAttribute(k_rnn, cudaFuncAttributeMaxDynamicSharedMemorySize, RNN_SMEM);
    cudaFuncSetAttribute(k_xgemm16, cudaFuncAttributeMaxDynamicSharedMemorySize, XG_SMEM);

    k_prep0<<<(4 * NR * DIN + 255) / 256, 256>>>(h0, Ax, Ah, bx, bh);
    dim3 gs(DIN / 128, NSPAR / 8, 8);
    k_spar<<<gs, 128>>>(Bx, Cx, Bh, Ch);
    k_prep1<<<(64 * DH * 64 + 255) / 256, 256>>>(x);
    dim3 gx(N4 / 128, (TSTEPS * NB) / 128);
    k_xgemm16<<<gx, 256, XG_SMEM>>>();
    k_rnn<<<RCTAS, 256, RNN_SMEM>>>(c0, out);
}

// round 14
// speedup vs baseline: 1.0101x; 1.0101x over previous
#include <cuda_runtime.h>
#include <cuda_fp16.h>
#include <cstdint>
#include <cstddef>

#define TSTEPS 512
#define NB     128
#define DIN    1024
#define DH     1024
#define NR     256
#define N4     4096
#define NSPAR  768
#define RCTAS  128        // 2 batch-halves x 64 N-tiles
#define KCH    128
#define NCH    8          // DH/KCH
#define HSTRB  272        // h row stride bytes (256 data + 16 pad)
#define WSTRB  288        // W k-pair row stride bytes (256 data + 32 pad)
#define HCHUNK (64 * HSTRB)          // 17408 per h stage
#define NSTG   4
#define WOFF   (NSTG * HCHUNK)       // 69632
#define WFULL  (512 * WSTRB)         // 147456
#define RNN_SMEM (WOFF + WFULL)      // 217088
// xgemm fp16 staging (3-stage, R11-proven)
#define XASTR  144
#define XBSTR  544
#define XSTG_BYTES (128 * XASTR + 32 * XBSTR)  // 35840
#define XG_SMEM (3 * XSTG_BYTES)               // 107520

// ---- static device scratch ----
__device__ float g_Wx[(size_t)N4 * DIN];
__device__ float g_Wh[(size_t)N4 * DH];
__device__ float g_bias[N4];
__device__ float g_preX[(size_t)TSTEPS * NB * N4];          // 1 GiB
__device__ __half g_xh[(size_t)TSTEPS * NB * DIN];          // x in fp16
__device__ __half g_Wxh[(size_t)32 * 512 * 256];            // [nblk][kpair][n*2+par]
__device__ __half g_Whs[(size_t)64 * 512 * 128];            // [ntile][kpair][n*2+par]
__device__ __half g_h[2][NB * DH];                          // h ping-pong (fp16)
__device__ unsigned g_barg[8];
__device__ unsigned g_root2[64];                            // per-bhalf root (stride 32)

// ================= helpers =================
__device__ __forceinline__ void mma_f16(float* c, const uint32_t* a, const uint32_t* b) {
    asm volatile("mma.sync.aligned.m16n8k16.row.col.f32.f16.f16.f32 "
                 "{%0,%1,%2,%3}, {%4,%5,%6,%7}, {%8,%9}, {%0,%1,%2,%3};"
                 : "+f"(c[0]), "+f"(c[1]), "+f"(c[2]), "+f"(c[3])
                 : "r"(a[0]), "r"(a[1]), "r"(a[2]), "r"(a[3]), "r"(b[0]), "r"(b[1]));
}
__device__ __forceinline__ float fsigmoid(float x) { return 1.0f / (1.0f + __expf(-x)); }

__device__ __forceinline__ uint32_t smem_u32(const void* p) {
    uint32_t a;
    asm("{ .reg .u64 t; cvta.to.shared.u64 t, %1; cvt.u32.u64 %0, t; }" : "=r"(a) : "l"(p));
    return a;
}
__device__ __forceinline__ void cp16(uint32_t dst, const void* src) {
    asm volatile("cp.async.cg.shared.global [%0], [%1], 16;" :: "r"(dst), "l"(src));
}
__device__ __forceinline__ unsigned ld_acq(const unsigned* p) {
    unsigned v;
    asm volatile("ld.acquire.gpu.global.u32 %0, [%1];" : "=r"(v) : "l"(p) : "memory");
    return v;
}
#define CP_COMMIT() asm volatile("cp.async.commit_group;" ::: "memory")
#define CP_WAIT(n)  asm volatile("cp.async.wait_group %0;" :: "n"(n) : "memory")

// ================= prep kernels (fused) =================
__global__ void k_prep0(const float* __restrict__ h0,
                        const float* __restrict__ Ax, const float* __restrict__ Ah,
                        const float* __restrict__ bx, const float* __restrict__ bh) {
    int i = blockIdx.x * blockDim.x + threadIdx.x;
    if (i < 4 * NR * DIN) {
        int k = i % DIN, row = i / DIN;
        int g = row / NR, j = row % NR;
        size_t w = ((size_t)(g * DH + j)) * DIN + k;
        g_Wx[w] = Ax[i];
        g_Wh[w] = Ah[i];
    }
    if (i < N4) g_bias[i] = bx[i] + bh[i];
    if (i < NB * DH) g_h[0][i] = __float2half_rn(h0[i]);
    if (i < 8) g_barg[i] = 0;
    if (i < 64) g_root2[i] = 0;
}

__global__ void k_spar(const float* __restrict__ Bx, const float* __restrict__ Cx,
                       const float* __restrict__ Bh, const float* __restrict__ Ch) {
    int z = blockIdx.z;
    int g = z & 3;
    const float* Bp = (z < 4) ? Bx : Bh;
    const float* Cp = (z < 4) ? Cx : Ch;
    float*       Wp = (z < 4) ? g_Wx : g_Wh;
    int m0  = blockIdx.y * 8;
    int col = blockIdx.x * 128 + threadIdx.x;

    __shared__ float Bs[8][NR];
    for (int i = threadIdx.x; i < 8 * NR; i += 128) {
        int mm = i / NR, rr = i % NR;
        Bs[mm][rr] = Bp[(size_t)(g * NSPAR + m0 + mm) * NR + rr];
    }
    __syncthreads();
    float acc[8];
#pragma unroll
    for (int mm = 0; mm < 8; mm++) acc[mm] = 0.0f;
    for (int r = 0; r < NR; ++r) {
        float cv = Cp[(size_t)(g * NR + r) * DIN + col];
#pragma unroll
        for (int mm = 0; mm < 8; mm++) acc[mm] += Bs[mm][r] * cv;
    }
#pragma unroll
    for (int mm = 0; mm < 8; mm++)
        Wp[(size_t)(g * DH + NR + m0 + mm) * DIN + col] = acc[mm];
}

// fused: pack Wh, pack Wx, convert x (16 x-elems per thread). 4,194,304 threads.
__global__ void k_prep1(const float* __restrict__ x) {
    int i = blockIdx.x * blockDim.x + threadIdx.x;
    if (i >= 64 * DH * 64) return;
    {   // Wh pack
        int n = i & 63, k = (i >> 6) & (DH - 1), ntile = i >> 16;
        int ng = (n >> 4) * DH + ntile * 16 + (n & 15);
        size_t dst = ((size_t)ntile * 512 + (k >> 1)) * 128 + n * 2 + (k & 1);
        g_Whs[dst] = __float2half_rn(g_Wh[(size_t)ng * DH + k]);
    }
    {   // Wx pack
        int k = i & (DIN - 1), n = i >> 10;
        int nb = n >> 7, nl = n & 127;
        size_t dst = ((size_t)nb * 512 + (k >> 1)) * 256 + nl * 2 + (k & 1);
        g_Wxh[dst] = __float2half_rn(g_Wx[(size_t)n * DIN + k]);
    }
    {   // x convert: 16 elems
        size_t base = (size_t)i * 16;
#pragma unroll
        for (int p = 0; p < 4; p++) {
            float4 v = *(const float4*)&x[base + p * 4];
            *(__half2*)&g_xh[base + p * 4]     = __floats2half2_rn(v.x, v.y);
            *(__half2*)&g_xh[base + p * 4 + 2] = __floats2half2_rn(v.z, v.w);
        }
    }
}

// ---------------- X GEMM fp16: preX = x @ Wx^T + bias (exact R11 version) ----------------
__global__ __launch_bounds__(256) void k_xgemm16() {
    extern __shared__ char xsm[];
    const int tid  = threadIdx.x;
    const int lane = tid & 31;
    const int warp = tid >> 5;
    const int wm   = warp & 1;
    const int wn   = warp >> 1;
    const int q    = lane & 3;
    const size_t mBase = (size_t)blockIdx.y * 128;
    const int    nb    = blockIdx.x;

    auto issue = [&](int cc) {
        uint32_t sb = smem_u32(xsm) + (cc % 3) * XSTG_BYTES;
#pragma unroll
        for (int i = 0; i < 8; i++) {
            int s = tid + i * 256;
            if (s < 1024) {
                int r = s >> 3, seg = s & 7;
                cp16(sb + (uint32_t)(r * XASTR + seg * 16),
                     &g_xh[(mBase + r) * DIN + cc * 64 + seg * 8]);
            } else {
                int v = s - 1024;
                int kl = v >> 5, seg = v & 31;
                cp16(sb + (uint32_t)(128 * XASTR + kl * XBSTR + seg * 16),
                     &g_Wxh[((size_t)nb * 512 + cc * 32 + kl) * 256 + seg * 8]);
            }
        }
        CP_COMMIT();
    };

    issue(0); issue(1); issue(2);

    float acc[4][4][4];
#pragma unroll
    for (int a = 0; a < 4; a++)
#pragma unroll
        for (int b = 0; b < 4; b++)
#pragma unroll
            for (int d = 0; d < 4; d++) acc[a][b][d] = 0.0f;

    for (int ch = 0; ch < 16; ++ch) {
        if (ch < 14)       CP_WAIT(2);
        else if (ch == 14) CP_WAIT(1);
        else               CP_WAIT(0);
        __syncthreads();

        const char* HsB = xsm + (ch % 3) * XSTG_BYTES;
        const char* WsB = HsB + 128 * XASTR;
#pragma unroll
        for (int k16 = 0; k16 < 4; k16++) {
            const int kb = k16 * 16;
            uint32_t af[4][4];
#pragma unroll
            for (int mf = 0; mf < 4; mf++) {
                int r0 = wm * 64 + mf * 16 + (lane >> 2);
                af[mf][0] = *(const uint32_t*)(HsB + r0 * XASTR + (kb + 2 * q) * 2);
                af[mf][1] = *(const uint32_t*)(HsB + (r0 + 8) * XASTR + (kb + 2 * q) * 2);
                af[mf][2] = *(const uint32_t*)(HsB + r0 * XASTR + (kb + 8 + 2 * q) * 2);
                af[mf][3] = *(const uint32_t*)(HsB + (r0 + 8) * XASTR + (kb + 8 + 2 * q) * 2);
            }
#pragma unroll
            for (int nf = 0; nf < 4; nf++) {
                uint32_t bf[2];
                int n0 = wn * 32 + nf * 8 + (lane >> 2);
                bf[0] = *(const uint32_t*)(WsB + (kb / 2 + q) * XBSTR + n0 * 4);
                bf[1] = *(const uint32_t*)(WsB + (kb / 2 + 4 + q) * XBSTR + n0 * 4);
#pragma unroll
                for (int mf = 0; mf < 4; mf++)
                    mma_f16(acc[mf][nf], af[mf], bf);
            }
        }
        __syncthreads();
        if (ch + 3 < 16) issue(ch + 3);
    }

    const int nBase = nb * 128;
#pragma unroll
    for (int mf = 0; mf < 4; mf++) {
#pragma unroll
        for (int nf = 0; nf < 4; nf++) {
            int r0 = wm * 64 + mf * 16 + (lane >> 2);
            int c0 = wn * 32 + nf * 8 + (lane & 3) * 2;
            int n  = nBase + c0;
            size_t base = (mBase + r0) * (size_t)N4 + n;
            g_preX[base]                      = acc[mf][nf][0] + g_bias[n];
            g_preX[base + 1]                  = acc[mf][nf][1] + g_bias[n + 1];
            g_preX[base + 8 * (size_t)N4]     = acc[mf][nf][2] + g_bias[n];
            g_preX[base + 8 * (size_t)N4 + 1] = acc[mf][nf][3] + g_bias[n + 1];
        }
    }
}

// ---------------- persistent M-split fp16 recurrence, W resident, 4-stage / 1 sync per chunk ----------------
__global__ __launch_bounds__(256) void k_rnn(const float* __restrict__ c0,
                                             float* __restrict__ out) {
    extern __shared__ char dsm[];
    const int tid   = threadIdx.x;
    const int lane  = tid & 31;
    const int warp  = tid >> 5;
    const int cta   = blockIdx.x;
    const int ntile = cta & 63;
    const int bhalf = cta >> 6;
    const int bh64  = bhalf * 64;
    const int wq    = warp & 3;
    const int kpar  = warp >> 2;
    const int wm    = wq & 1;
    const int wn    = wq >> 1;
    const int q     = lane & 3;
    float* Psa = (float*)dsm;                    // overlay on h stage 0
    float* Psb = (float*)(dsm + HCHUNK);         // overlay on h stage 1

    const uint32_t dynb = smem_u32(dsm);

    const int er = tid & 63;
    const int ug = tid >> 6;
    const int eb = bh64 + er;

    // load resident W
    for (int i = tid; i < 8192; i += 256) {
        int row = i >> 4, seg = i & 15;
        cp16(dynb + (uint32_t)(WOFF + row * WSTRB + seg * 16),
             &g_Whs[((size_t)ntile * 512 + row) * 128 + seg * 8]);
    }
    CP_COMMIT();

    float cst[4];
    {
        float4 cv = *(const float4*)&c0[(size_t)eb * DH + ntile * 16 + ug * 4];
        cst[0] = cv.x; cst[1] = cv.y; cst[2] = cv.z; cst[3] = cv.w;
    }
    CP_WAIT(0);
    __syncthreads();

    for (int t = 0; t < TSTEPS; ++t) {
        const int src = t & 1;
        const __half* __restrict__ hsrc = g_h[src];

        auto issue = [&](int cc) {
            uint32_t sb = dynb + (cc & 3) * HCHUNK;
#pragma unroll
            for (int i = 0; i < 4; i++) {
                int s = tid + i * 256;
                int r = s >> 4, seg = s & 15;
                cp16(sb + (uint32_t)(r * HSTRB + seg * 16),
                     &hsrc[(size_t)(bh64 + r) * DH + cc * KCH + seg * 8]);
            }
            CP_COMMIT();
        };

        issue(0); issue(1); issue(2);

        float4 px[4];
        {
            size_t pxb = ((size_t)t * NB + eb) * N4 + ntile * 16 + ug * 4;
#pragma unroll
            for (int g = 0; g < 4; g++)
                px[g] = *(const float4*)&g_preX[pxb + (size_t)g * DH];
        }

        float acc[2][4][4];
#pragma unroll
        for (int a = 0; a < 2; a++)
#pragma unroll
            for (int c = 0; c < 4; c++)
#pragma unroll
                for (int d = 0; d < 4; d++) acc[a][c][d] = 0.0f;

        for (int ch = 0; ch < NCH; ++ch) {
            if (ch <= NCH - 3)      CP_WAIT(2);
            else if (ch == NCH - 2) CP_WAIT(1);
            else                    CP_WAIT(0);
            __syncthreads();
            if (ch + 3 < NCH) issue(ch + 3);     // overwrites stage (ch-1)&3, protected by the sync above

            const char* HsB = dsm + (ch & 3) * HCHUNK;
            const char* WsB = dsm + WOFF + ch * 64 * WSTRB;
#pragma unroll
            for (int k16 = 0; k16 < 8; k16 += 2) {
                const int kb = (k16 + kpar) * 16;
                uint32_t af[2][4];
#pragma unroll
                for (int mf = 0; mf < 2; mf++) {
                    int r0 = wm * 32 + mf * 16 + (lane >> 2);
                    af[mf][0] = *(const uint32_t*)(HsB + r0 * HSTRB + (kb + 2 * q) * 2);
                    af[mf][1] = *(const uint32_t*)(HsB + (r0 + 8) * HSTRB + (kb + 2 * q) * 2);
                    af[mf][2] = *(const uint32_t*)(HsB + r0 * HSTRB + (kb + 8 + 2 * q) * 2);
                    af[mf][3] = *(const uint32_t*)(HsB + (r0 + 8) * HSTRB + (kb + 8 + 2 * q) * 2);
                }
#pragma unroll
                for (int nf = 0; nf < 4; nf++) {
                    uint32_t bf[2];
                    int n0 = wn * 32 + nf * 8 + (lane >> 2);
                    bf[0] = *(const uint32_t*)(WsB + (kb / 2 + q) * WSTRB + n0 * 4);
                    bf[1] = *(const uint32_t*)(WsB + (kb / 2 + 4 + q) * WSTRB + n0 * 4);
#pragma unroll
                    for (int mf = 0; mf < 2; mf++)
                        mma_f16(acc[mf][nf], af[mf], bf);
                }
            }
        }
        __syncthreads();   // all warps done reading stages 0/1 before Ps overlay

        // single-sync merge: kpar groups store to disjoint Ps arrays
        {
            float* Pd = (kpar == 0) ? Psa : Psb;
#pragma unroll
            for (int mf = 0; mf < 2; mf++) {
#pragma unroll
                for (int nf = 0; nf < 4; nf++) {
                    int r0 = wm * 32 + mf * 16 + (lane >> 2);
                    int c0i = wn * 32 + nf * 8 + q * 2;
                    Pd[r0 * 68 + c0i]           = acc[mf][nf][0];
                    Pd[r0 * 68 + c0i + 1]       = acc[mf][nf][1];
                    Pd[(r0 + 8) * 68 + c0i]     = acc[mf][nf][2];
                    Pd[(r0 + 8) * 68 + c0i + 1] = acc[mf][nf][3];
                }
            }
        }
        __syncthreads();

        // pointwise LSTM (float4 Ps reads)
        float hv[4];
        {
            float4 pa0 = *(const float4*)&Psa[er * 68 + ug * 4];
            float4 pa1 = *(const float4*)&Psa[er * 68 + 16 + ug * 4];
            float4 pa2 = *(const float4*)&Psa[er * 68 + 32 + ug * 4];
            float4 pa3 = *(const float4*)&Psa[er * 68 + 48 + ug * 4];
            float4 pb0 = *(const float4*)&Psb[er * 68 + ug * 4];
            float4 pb1 = *(const float4*)&Psb[er * 68 + 16 + ug * 4];
            float4 pb2 = *(const float4*)&Psb[er * 68 + 32 + ug * 4];
            float4 pb3 = *(const float4*)&Psb[er * 68 + 48 + ug * 4];
#pragma unroll
            for (int i = 0; i < 4; i++) {
                float f  = fsigmoid(((const float*)&pa0)[i] + ((const float*)&pb0)[i] + ((const float*)&px[0])[i]);
                float ii = fsigmoid(((const float*)&pa1)[i] + ((const float*)&pb1)[i] + ((const float*)&px[1])[i]);
                float gg = tanhf(((const float*)&pa2)[i] + ((const float*)&pb2)[i] + ((const float*)&px[2])[i]);
                float oo = fsigmoid(((const float*)&pa3)[i] + ((const float*)&pb3)[i] + ((const float*)&px[3])[i]);
                float nc = f * cst[i] + ii * gg;
                cst[i] = nc;
                hv[i] = oo * tanhf(nc);
            }
            // h ping-pong store FIRST (covered by the fence below)
            __half* __restrict__ hdst = g_h[src ^ 1];
            size_t hb = (size_t)eb * DH + ntile * 16 + ug * 4;
            *(__half2*)&hdst[hb]     = __floats2half2_rn(hv[0], hv[1]);
            *(__half2*)&hdst[hb + 2] = __floats2half2_rn(hv[2], hv[3]);
        }

        __threadfence();
        __syncthreads();
        if (tid == 0) {
            unsigned r = atomicAdd(&g_barg[cta >> 4], 1u);
            if (r == 16u * (unsigned)(t + 1) - 1u) {
                __threadfence();
                atomicAdd(&g_root2[bhalf * 32], 1u);
            }
        }
        // out stores overlap the barrier spin
        {
            size_t oo = ((size_t)t * NB + eb) * DH + ntile * 16 + ug * 4;
            *(float4*)&out[oo] = make_float4(hv[0], hv[1], hv[2], hv[3]);
            if (t == TSTEPS - 1) {
                size_t fb = (size_t)TSTEPS * NB * DH + (size_t)eb * DH + ntile * 16 + ug * 4;
                *(float4*)&out[fb] = make_float4(hv[0], hv[1], hv[2], hv[3]);
                *(float4*)&out[fb + (size_t)NB * DH] = make_float4(cst[0], cst[1], cst[2], cst[3]);
            }
        }
        if (tid == 0) {
            while (ld_acq(&g_root2[bhalf * 32]) < 4u * (unsigned)(t + 1)) { }
        }
        __syncthreads();
    }
}

// ---------------- launch ----------------
extern "C" void kernel_launch(void* const* d_in, const int* in_sizes, int n_in,
                              void* d_out, int out_size) {
    const float* x  = (const float*)d_in[0];
    const float* h0 = (const float*)d_in[1];
    const float* c0 = (const float*)d_in[2];
    const float* Ax = (const float*)d_in[3];
    const float* Bx = (const float*)d_in[4];
    const float* Cx = (const float*)d_in[5];
    const float* Ah = (const float*)d_in[6];
    const float* Bh = (const float*)d_in[7];
    const float* Ch = (const float*)d_in[8];
    const float* bx = (const float*)d_in[9];
    const float* bh = (const float*)d_in[10];
    float* out = (float*)d_out;

    cudaFuncSetAttribute(k_rnn, cudaFuncAttributeMaxDynamicSharedMemorySize, RNN_SMEM);
    cudaFuncSetAttribute(k_xgemm16, cudaFuncAttributeMaxDynamicSharedMemorySize, XG_SMEM);

    k_prep0<<<(4 * NR * DIN + 255) / 256, 256>>>(h0, Ax, Ah, bx, bh);
    dim3 gs(DIN / 128, NSPAR / 8, 8);
    k_spar<<<gs, 128>>>(Bx, Cx, Bh, Ch);
    k_prep1<<<(64 * DH * 64 + 255) / 256, 256>>>(x);
    dim3 gx(N4 / 128, (TSTEPS * NB) / 128);
    k_xgemm16<<<gx, 256, XG_SMEM>>>();
    k_rnn<<<RCTAS, 256, RNN_SMEM>>>(c0, out);
}

// round 15
// speedup vs baseline: 1.0377x; 1.0274x over previous
#include <cuda_runtime.h>
#include <cuda_fp16.h>
#include <cstdint>
#include <cstddef>

#define TSTEPS 512
#define NB     128
#define DIN    1024
#define DH     1024
#define NR     256
#define N4     4096
#define NSPAR  768
#define RCTAS  128        // 2 batch-halves x 64 N-tiles
#define KCH    128
#define NCH    8          // DH/KCH
#define HSTRB  272        // h row stride bytes (256 data + 16 pad)
#define WSTRB  288        // W k-pair row stride bytes (256 data + 32 pad)
#define HCHUNK (64 * HSTRB)          // 17408 per h stage
#define WOFF   (3 * HCHUNK)          // 52224
#define WFULL  (512 * WSTRB)         // 147456
#define RNN_SMEM (WOFF + WFULL)      // 199680
// xgemm fp16 staging (3-stage, 2 CTAs/SM)
#define XASTR  144
#define XBSTR  544
#define XSTG_BYTES (128 * XASTR + 32 * XBSTR)  // 35840
#define XG_SMEM (3 * XSTG_BYTES)               // 107520

// ---- static device scratch ----
__device__ float g_Wx[(size_t)N4 * DIN];
__device__ float g_Wh[(size_t)N4 * DH];
__device__ float g_bias[N4];
__device__ float g_preX[(size_t)TSTEPS * NB * N4];          // 1 GiB
__device__ __half g_xh[(size_t)TSTEPS * NB * DIN];          // x in fp16
__device__ __half g_Wxh[(size_t)32 * 512 * 256];            // [nblk][kpair][n*2+par]
__device__ __half g_Whs[(size_t)64 * 512 * 128];            // [ntile][kpair][n*2+par]
__device__ __half g_h[2][NB * DH];                          // h ping-pong (fp16)
__device__ unsigned g_barg[8];
__device__ unsigned g_root2[64];                            // per-bhalf root (stride 32)

// ================= helpers =================
__device__ __forceinline__ void mma_f16(float* c, const uint32_t* a, const uint32_t* b) {
    asm volatile("mma.sync.aligned.m16n8k16.row.col.f32.f16.f16.f32 "
                 "{%0,%1,%2,%3}, {%4,%5,%6,%7}, {%8,%9}, {%0,%1,%2,%3};"
                 : "+f"(c[0]), "+f"(c[1]), "+f"(c[2]), "+f"(c[3])
                 : "r"(a[0]), "r"(a[1]), "r"(a[2]), "r"(a[3]), "r"(b[0]), "r"(b[1]));
}
__device__ __forceinline__ void ldsm4(uint32_t* r, uint32_t addr) {
    asm volatile("ldmatrix.sync.aligned.m8n8.x4.shared.b16 {%0,%1,%2,%3}, [%4];"
                 : "=r"(r[0]), "=r"(r[1]), "=r"(r[2]), "=r"(r[3]) : "r"(addr));
}
__device__ __forceinline__ float fsigmoid(float x) { return 1.0f / (1.0f + __expf(-x)); }

__device__ __forceinline__ uint32_t smem_u32(const void* p) {
    uint32_t a;
    asm("{ .reg .u64 t; cvta.to.shared.u64 t, %1; cvt.u32.u64 %0, t; }" : "=r"(a) : "l"(p));
    return a;
}
__device__ __forceinline__ void cp16(uint32_t dst, const void* src) {
    asm volatile("cp.async.cg.shared.global [%0], [%1], 16;" :: "r"(dst), "l"(src));
}
__device__ __forceinline__ unsigned ld_acq(const unsigned* p) {
    unsigned v;
    asm volatile("ld.acquire.gpu.global.u32 %0, [%1];" : "=r"(v) : "l"(p) : "memory");
    return v;
}
#define CP_COMMIT() asm volatile("cp.async.commit_group;" ::: "memory")
#define CP_WAIT(n)  asm volatile("cp.async.wait_group %0;" :: "n"(n) : "memory")

// ================= prep kernels (fused) =================
__global__ void k_prep0(const float* __restrict__ h0,
                        const float* __restrict__ Ax, const float* __restrict__ Ah,
                        const float* __restrict__ bx, const float* __restrict__ bh) {
    int i = blockIdx.x * blockDim.x + threadIdx.x;
    if (i < 4 * NR * DIN) {
        int k = i % DIN, row = i / DIN;
        int g = row / NR, j = row % NR;
        size_t w = ((size_t)(g * DH + j)) * DIN + k;
        g_Wx[w] = Ax[i];
        g_Wh[w] = Ah[i];
    }
    if (i < N4) g_bias[i] = bx[i] + bh[i];
    if (i < NB * DH) g_h[0][i] = __float2half_rn(h0[i]);
    if (i < 8) g_barg[i] = 0;
    if (i < 64) g_root2[i] = 0;
}

__global__ void k_spar(const float* __restrict__ Bx, const float* __restrict__ Cx,
                       const float* __restrict__ Bh, const float* __restrict__ Ch) {
    int z = blockIdx.z;
    int g = z & 3;
    const float* Bp = (z < 4) ? Bx : Bh;
    const float* Cp = (z < 4) ? Cx : Ch;
    float*       Wp = (z < 4) ? g_Wx : g_Wh;
    int m0  = blockIdx.y * 8;
    int col = blockIdx.x * 128 + threadIdx.x;

    __shared__ float Bs[8][NR];
    for (int i = threadIdx.x; i < 8 * NR; i += 128) {
        int mm = i / NR, rr = i % NR;
        Bs[mm][rr] = Bp[(size_t)(g * NSPAR + m0 + mm) * NR + rr];
    }
    __syncthreads();
    float acc[8];
#pragma unroll
    for (int mm = 0; mm < 8; mm++) acc[mm] = 0.0f;
    for (int r = 0; r < NR; ++r) {
        float cv = Cp[(size_t)(g * NR + r) * DIN + col];
#pragma unroll
        for (int mm = 0; mm < 8; mm++) acc[mm] += Bs[mm][r] * cv;
    }
#pragma unroll
    for (int mm = 0; mm < 8; mm++)
        Wp[(size_t)(g * DH + NR + m0 + mm) * DIN + col] = acc[mm];
}

// fused: pack Wh, pack Wx, convert x (16 x-elems per thread).
__global__ void k_prep1(const float* __restrict__ x) {
    int i = blockIdx.x * blockDim.x + threadIdx.x;
    if (i >= 64 * DH * 64) return;
    {   // Wh pack
        int n = i & 63, k = (i >> 6) & (DH - 1), ntile = i >> 16;
        int ng = (n >> 4) * DH + ntile * 16 + (n & 15);
        size_t dst = ((size_t)ntile * 512 + (k >> 1)) * 128 + n * 2 + (k & 1);
        g_Whs[dst] = __float2half_rn(g_Wh[(size_t)ng * DH + k]);
    }
    {   // Wx pack
        int k = i & (DIN - 1), n = i >> 10;
        int nb = n >> 7, nl = n & 127;
        size_t dst = ((size_t)nb * 512 + (k >> 1)) * 256 + nl * 2 + (k & 1);
        g_Wxh[dst] = __float2half_rn(g_Wx[(size_t)n * DIN + k]);
    }
    {   // x convert: 16 elems
        size_t base = (size_t)i * 16;
#pragma unroll
        for (int p = 0; p < 4; p++) {
            float4 v = *(const float4*)&x[base + p * 4];
            *(__half2*)&g_xh[base + p * 4]     = __floats2half2_rn(v.x, v.y);
            *(__half2*)&g_xh[base + p * 4 + 2] = __floats2half2_rn(v.z, v.w);
        }
    }
}

// ---------------- X GEMM fp16: preX = x @ Wx^T + bias ----------------
// R11 structure (3-stage, 2 syncs/chunk, 2 CTAs/SM) + ldmatrix.x4 A-fragments.
__global__ __launch_bounds__(256) void k_xgemm16() {
    extern __shared__ char xsm[];
    const int tid  = threadIdx.x;
    const int lane = tid & 31;
    const int warp = tid >> 5;
    const int wm   = warp & 1;
    const int wn   = warp >> 1;
    const int q    = lane & 3;
    const size_t mBase = (size_t)blockIdx.y * 128;
    const int    nb    = blockIdx.x;
    const uint32_t xb  = smem_u32(xsm);

    auto issue = [&](int cc) {
        uint32_t sb = xb + (cc % 3) * XSTG_BYTES;
#pragma unroll
        for (int i = 0; i < 8; i++) {
            int s = tid + i * 256;
            if (s < 1024) {
                int r = s >> 3, seg = s & 7;
                cp16(sb + (uint32_t)(r * XASTR + seg * 16),
                     &g_xh[(mBase + r) * DIN + cc * 64 + seg * 8]);
            } else {
                int v = s - 1024;
                int kl = v >> 5, seg = v & 31;
                cp16(sb + (uint32_t)(128 * XASTR + kl * XBSTR + seg * 16),
                     &g_Wxh[((size_t)nb * 512 + cc * 32 + kl) * 256 + seg * 8]);
            }
        }
        CP_COMMIT();
    };

    issue(0); issue(1); issue(2);

    float acc[4][4][4];
#pragma unroll
    for (int a = 0; a < 4; a++)
#pragma unroll
        for (int b = 0; b < 4; b++)
#pragma unroll
            for (int d = 0; d < 4; d++) acc[a][b][d] = 0.0f;

    const int lrow = (lane & 7) + ((lane >> 3) & 1) * 8;   // ldmatrix row within 16
    const int lcol = (lane >> 4) * 8;                       // ldmatrix k-offset

    for (int ch = 0; ch < 16; ++ch) {
        if (ch < 14)       CP_WAIT(2);
        else if (ch == 14) CP_WAIT(1);
        else               CP_WAIT(0);
        __syncthreads();

        const uint32_t hsb = xb + (ch % 3) * XSTG_BYTES;
        const char* WsB = xsm + (ch % 3) * XSTG_BYTES + 128 * XASTR;
#pragma unroll
        for (int k16 = 0; k16 < 4; k16++) {
            const int kb = k16 * 16;
            uint32_t af[4][4];
#pragma unroll
            for (int mf = 0; mf < 4; mf++) {
                uint32_t ad = hsb + (uint32_t)((wm * 64 + mf * 16 + lrow) * XASTR + (kb + lcol) * 2);
                ldsm4(af[mf], ad);
            }
#pragma unroll
            for (int nf = 0; nf < 4; nf++) {
                uint32_t bf[2];
                int n0 = wn * 32 + nf * 8 + (lane >> 2);
                bf[0] = *(const uint32_t*)(WsB + (kb / 2 + q) * XBSTR + n0 * 4);
                bf[1] = *(const uint32_t*)(WsB + (kb / 2 + 4 + q) * XBSTR + n0 * 4);
#pragma unroll
                for (int mf = 0; mf < 4; mf++)
                    mma_f16(acc[mf][nf], af[mf], bf);
            }
        }
        __syncthreads();
        if (ch + 3 < 16) issue(ch + 3);
    }

    const int nBase = nb * 128;
#pragma unroll
    for (int mf = 0; mf < 4; mf++) {
#pragma unroll
        for (int nf = 0; nf < 4; nf++) {
            int r0 = wm * 64 + mf * 16 + (lane >> 2);
            int c0 = wn * 32 + nf * 8 + (lane & 3) * 2;
            int n  = nBase + c0;
            size_t base = (mBase + r0) * (size_t)N4 + n;
            g_preX[base]                      = acc[mf][nf][0] + g_bias[n];
            g_preX[base + 1]                  = acc[mf][nf][1] + g_bias[n + 1];
            g_preX[base + 8 * (size_t)N4]     = acc[mf][nf][2] + g_bias[n];
            g_preX[base + 8 * (size_t)N4 + 1] = acc[mf][nf][3] + g_bias[n + 1];
        }
    }
}

// ---------------- persistent M-split fp16 recurrence (EXACT R11 champion) ----------------
__global__ __launch_bounds__(256) void k_rnn(const float* __restrict__ c0,
                                             float* __restrict__ out) {
    extern __shared__ char dsm[];
    const int tid   = threadIdx.x;
    const int lane  = tid & 31;
    const int warp  = tid >> 5;
    const int cta   = blockIdx.x;
    const int ntile = cta & 63;
    const int bhalf = cta >> 6;
    const int bh64  = bhalf * 64;
    const int wq    = warp & 3;
    const int kpar  = warp >> 2;
    const int wm    = wq & 1;
    const int wn    = wq >> 1;
    const int q     = lane & 3;
    float* Psa = (float*)dsm;                    // overlay on h stage 0
    float* Psb = (float*)(dsm + HCHUNK);         // overlay on h stage 1

    const uint32_t dynb = smem_u32(dsm);

    const int er = tid & 63;
    const int ug = tid >> 6;
    const int eb = bh64 + er;

    // load resident W
    for (int i = tid; i < 8192; i += 256) {
        int row = i >> 4, seg = i & 15;
        cp16(dynb + (uint32_t)(WOFF + row * WSTRB + seg * 16),
             &g_Whs[((size_t)ntile * 512 + row) * 128 + seg * 8]);
    }
    CP_COMMIT();

    float cst[4];
    {
        float4 cv = *(const float4*)&c0[(size_t)eb * DH + ntile * 16 + ug * 4];
        cst[0] = cv.x; cst[1] = cv.y; cst[2] = cv.z; cst[3] = cv.w;
    }
    CP_WAIT(0);
    __syncthreads();

    for (int t = 0; t < TSTEPS; ++t) {
        const int src = t & 1;
        const __half* __restrict__ hsrc = g_h[src];

        auto issue = [&](int cc) {
            uint32_t sb = dynb + (cc % 3) * HCHUNK;
#pragma unroll
            for (int i = 0; i < 4; i++) {
                int s = tid + i * 256;
                int r = s >> 4, seg = s & 15;
                cp16(sb + (uint32_t)(r * HSTRB + seg * 16),
                     &hsrc[(size_t)(bh64 + r) * DH + cc * KCH + seg * 8]);
            }
            CP_COMMIT();
        };

        issue(0); issue(1); issue(2);

        float4 px[4];
        {
            size_t pxb = ((size_t)t * NB + eb) * N4 + ntile * 16 + ug * 4;
#pragma unroll
            for (int g = 0; g < 4; g++)
                px[g] = *(const float4*)&g_preX[pxb + (size_t)g * DH];
        }

        float acc[2][4][4];
#pragma unroll
        for (int a = 0; a < 2; a++)
#pragma unroll
            for (int c = 0; c < 4; c++)
#pragma unroll
                for (int d = 0; d < 4; d++) acc[a][c][d] = 0.0f;

        for (int ch = 0; ch < NCH; ++ch) {
            if (ch < NCH - 2)       CP_WAIT(2);
            else if (ch == NCH - 2) CP_WAIT(1);
            else                    CP_WAIT(0);
            __syncthreads();

            const char* HsB = dsm + (ch % 3) * HCHUNK;
            const char* WsB = dsm + WOFF + ch * 64 * WSTRB;
#pragma unroll
            for (int k16 = 0; k16 < 8; k16 += 2) {
                const int kb = (k16 + kpar) * 16;
                uint32_t af[2][4];
#pragma unroll
                for (int mf = 0; mf < 2; mf++) {
                    int r0 = wm * 32 + mf * 16 + (lane >> 2);
                    af[mf][0] = *(const uint32_t*)(HsB + r0 * HSTRB + (kb + 2 * q) * 2);
                    af[mf][1] = *(const uint32_t*)(HsB + (r0 + 8) * HSTRB + (kb + 2 * q) * 2);
                    af[mf][2] = *(const uint32_t*)(HsB + r0 * HSTRB + (kb + 8 + 2 * q) * 2);
                    af[mf][3] = *(const uint32_t*)(HsB + (r0 + 8) * HSTRB + (kb + 8 + 2 * q) * 2);
                }
#pragma unroll
                for (int nf = 0; nf < 4; nf++) {
                    uint32_t bf[2];
                    int n0 = wn * 32 + nf * 8 + (lane >> 2);
                    bf[0] = *(const uint32_t*)(WsB + (kb / 2 + q) * WSTRB + n0 * 4);
                    bf[1] = *(const uint32_t*)(WsB + (kb / 2 + 4 + q) * WSTRB + n0 * 4);
#pragma unroll
                    for (int mf = 0; mf < 2; mf++)
                        mma_f16(acc[mf][nf], af[mf], bf);
                }
            }
            __syncthreads();
            if (ch + 3 < NCH) issue(ch + 3);
        }

        // single-sync merge: kpar groups store to disjoint Ps arrays
        {
            float* Pd = (kpar == 0) ? Psa : Psb;
#pragma unroll
            for (int mf = 0; mf < 2; mf++) {
#pragma unroll
                for (int nf = 0; nf < 4; nf++) {
                    int r0 = wm * 32 + mf * 16 + (lane >> 2);
                    int c0i = wn * 32 + nf * 8 + q * 2;
                    Pd[r0 * 68 + c0i]           = acc[mf][nf][0];
                    Pd[r0 * 68 + c0i + 1]       = acc[mf][nf][1];
                    Pd[(r0 + 8) * 68 + c0i]     = acc[mf][nf][2];
                    Pd[(r0 + 8) * 68 + c0i + 1] = acc[mf][nf][3];
                }
            }
        }
        __syncthreads();

        // pointwise LSTM: thread -> (row er, units ug*4..+3)
        {
            __half* __restrict__ hdst = g_h[src ^ 1];
            float hv[4];
#pragma unroll
            for (int i = 0; i < 4; i++) {
                int jc = ug * 4 + i;
                float pf = Psa[er * 68 + jc]      + Psb[er * 68 + jc];
                float pi = Psa[er * 68 + 16 + jc] + Psb[er * 68 + 16 + jc];
                float pg = Psa[er * 68 + 32 + jc] + Psb[er * 68 + 32 + jc];
                float po = Psa[er * 68 + 48 + jc] + Psb[er * 68 + 48 + jc];
                float f  = fsigmoid(pf + ((const float*)&px[0])[i]);
                float ii = fsigmoid(pi + ((const float*)&px[1])[i]);
                float gg = tanhf(pg + ((const float*)&px[2])[i]);
                float oo = fsigmoid(po + ((const float*)&px[3])[i]);
                float nc = f * cst[i] + ii * gg;
                cst[i] = nc;
                hv[i] = oo * tanhf(nc);
            }
            size_t oo = ((size_t)t * NB + eb) * DH + ntile * 16 + ug * 4;
            *(float4*)&out[oo] = make_float4(hv[0], hv[1], hv[2], hv[3]);
            __half2 h2a = __floats2half2_rn(hv[0], hv[1]);
            __half2 h2b = __floats2half2_rn(hv[2], hv[3]);
            size_t hb = (size_t)eb * DH + ntile * 16 + ug * 4;
            *(__half2*)&hdst[hb]     = h2a;
            *(__half2*)&hdst[hb + 2] = h2b;
            if (t == TSTEPS - 1) {
                size_t fb = (size_t)TSTEPS * NB * DH + (size_t)eb * DH + ntile * 16 + ug * 4;
                *(float4*)&out[fb] = make_float4(hv[0], hv[1], hv[2], hv[3]);
                *(float4*)&out[fb + (size_t)NB * DH] = make_float4(cst[0], cst[1], cst[2], cst[3]);
            }
        }

        // per-bhalf two-level barrier
        __threadfence();
        __syncthreads();
        if (tid == 0) {
            unsigned r = atomicAdd(&g_barg[cta >> 4], 1u);
            if (r == 16u * (unsigned)(t + 1) - 1u) {
                __threadfence();
                atomicAdd(&g_root2[bhalf * 32], 1u);
            }
            while (ld_acq(&g_root2[bhalf * 32]) < 4u * (unsigned)(t + 1)) { }
        }
        __syncthreads();
    }
}

// ---------------- launch ----------------
extern "C" void kernel_launch(void* const* d_in, const int* in_sizes, int n_in,
                              void* d_out, int out_size) {
    const float* x  = (const float*)d_in[0];
    const float* h0 = (const float*)d_in[1];
    const float* c0 = (const float*)d_in[2];
    const float* Ax = (const float*)d_in[3];
    const float* Bx = (const float*)d_in[4];
    const float* Cx = (const float*)d_in[5];
    const float* Ah = (const float*)d_in[6];
    const float* Bh = (const float*)d_in[7];
    const float* Ch = (const float*)d_in[8];
    const float* bx = (const float*)d_in[9];
    const float* bh = (const float*)d_in[10];
    float* out = (float*)d_out;

    cudaFuncSetAttribute(k_rnn, cudaFuncAttributeMaxDynamicSharedMemorySize, RNN_SMEM);
    cudaFuncSetAttribute(k_xgemm16, cudaFuncAttributeMaxDynamicSharedMemorySize, XG_SMEM);

    k_prep0<<<(4 * NR * DIN + 255) / 256, 256>>>(h0, Ax, Ah, bx, bh);
    dim3 gs(DIN / 128, NSPAR / 8, 8);
    k_spar<<<gs, 128>>>(Bx, Cx, Bh, Ch);
    k_prep1<<<(64 * DH * 64 + 255) / 256, 256>>>(x);
    dim3 gx(N4 / 128, (TSTEPS * NB) / 128);
    k_xgemm16<<<gx, 256, XG_SMEM>>>();
    k_rnn<<<RCTAS, 256, RNN_SMEM>>>(c0, out);
}